// round 9
// baseline (speedup 1.0000x reference)
#include <cuda_runtime.h>

// Problem constants (fixed by reference setup_inputs)
#define B_TOT  16384
#define P_DIM  32
#define N_DIM  2
#define CIN    9
#define COUT   64
#define PJ     64          // P*N = BatchNorm column count
#define NPAIR  45          // upper-tri pairs of 9x9
#define NSLC   8           // global accumulator slices
#define GRIDM  1024        // k_main grid (16 b per block)
#define EPSV   1e-5f

typedef unsigned long long ull;

// Device scratch. Zero at the start of every call:
//  - first call: static zero-init
//  - later calls: k_main's elected last block zeroes g_pm/g_pe and resets g_t2
//    AFTER all blocks have read them (ticket == GRIDM-1 implies all prologues
//    completed, since each block's prologue precedes its epilogue).
__device__ float g_pm[NSLC][PJ];     // mean partials (slices)
__device__ float g_pe[NSLC][PJ];     // ex2 partials (slices)
__device__ unsigned g_t2;            // k_main done ticket

// ---------------------------------------------------------------------------
// f32x2 packed helpers (Blackwell sm_103a packed fp32 pipe)
// ---------------------------------------------------------------------------
__device__ __forceinline__ ull pk2(float lo, float hi) {
    ull r;
    asm("mov.b64 %0,{%1,%2};" : "=l"(r) : "f"(lo), "f"(hi));
    return r;
}
__device__ __forceinline__ void upk2(ull v, float& lo, float& hi) {
    asm("mov.b64 {%0,%1},%2;" : "=f"(lo), "=f"(hi) : "l"(v));
}
__device__ __forceinline__ void cp16(void* s, const void* g) {
    unsigned sa = (unsigned)__cvta_generic_to_shared(s);
    asm volatile("cp.async.cg.shared.global [%0], [%1], 16;" :: "r"(sa), "l"(g));
}
#define CP_COMMIT() asm volatile("cp.async.commit_group;")
#define CP_WAIT1()  asm volatile("cp.async.wait_group 1;")
#define CP_WAIT0()  asm volatile("cp.async.wait_group 0;")

// ---------------------------------------------------------------------------
// Kernel 1: per-block contracted BN stats (identical to the passing R5 body).
//   mean_part[j] = sum_b sum_c p[b,j,c] * wsum[c]
//   ex2_part[j]  = sum_b sum_{c1<=c2} p_c1 p_c2 * G2[c1c2],  G2 = (2-[c1==c2])*W^T W
// 512 blocks x 256 threads, 4 sweeps of 8 rows, cp.async double-buffered.
// ---------------------------------------------------------------------------
__global__ __launch_bounds__(256) void k_stats(const float* __restrict__ pil,
                                               const float* __restrict__ W) {
    __shared__ float4 buf[2][1152];          // 2 x 8 rows x 576 floats = 36.9 KB
    __shared__ float sG2[NPAIR];
    __shared__ float swsum[CIN];
    __shared__ float smean[256];
    __shared__ float sex2[256];
    const int tid = threadIdx.x;
    const int j = tid & 63;
    const int g = tid >> 6;                  // 0..3

    // Stage sweep 0 asynchronously
    {
        const float4* src = (const float4*)(pil + (size_t)(blockIdx.x * 8) * 576);
        for (int i = tid; i < 1152; i += 256) cp16(&buf[0][i], &src[i]);
        CP_COMMIT();
    }

    // Gram (doubled off-diagonals) + column sums of W — overlaps the cp.async
    if (tid < NPAIR) {
        int c1 = 0, c2 = 0, idx = 0;
#pragma unroll
        for (int a = 0; a < CIN; a++)
#pragma unroll
            for (int b2 = a; b2 < CIN; b2++) {
                if (idx == tid) { c1 = a; c2 = b2; }
                idx++;
            }
        float s = 0.0f;
        for (int o = 0; o < COUT; o++) s += W[o * CIN + c1] * W[o * CIN + c2];
        sG2[tid] = (c1 == c2 ? 1.0f : 2.0f) * s;
    } else if (tid < NPAIR + CIN) {
        const int c = tid - NPAIR;
        float s = 0.0f;
        for (int o = 0; o < COUT; o++) s += W[o * CIN + c];
        swsum[c] = s;
    }

    float s1[CIN];
    float s2[NPAIR];
#pragma unroll
    for (int k = 0; k < CIN; k++) s1[k] = 0.0f;
#pragma unroll
    for (int k = 0; k < NPAIR; k++) s2[k] = 0.0f;

    for (int s = 0; s < 4; s++) {
        if (s < 3) {
            const float4* src =
                (const float4*)(pil + (size_t)((s + 1) * 4096 + blockIdx.x * 8) * 576);
            for (int i = tid; i < 1152; i += 256) cp16(&buf[(s + 1) & 1][i], &src[i]);
            CP_COMMIT();
            CP_WAIT1();                      // sweep s complete, s+1 may be in flight
        } else {
            CP_WAIT0();
        }
        __syncthreads();

        const float* base = (const float*)buf[s & 1];
#pragma unroll
        for (int half = 0; half < 2; half++) {
            const float* v = base + (g + 4 * half) * 576 + j * CIN;
            float vv[CIN];
#pragma unroll
            for (int k = 0; k < CIN; k++) vv[k] = v[k];
            int idx = 0;
#pragma unroll
            for (int c1 = 0; c1 < CIN; c1++) {
                s1[c1] += vv[c1];
#pragma unroll
                for (int c2 = c1; c2 < CIN; c2++) { s2[idx] += vv[c1] * vv[c2]; idx++; }
            }
        }
        __syncthreads();                     // buf[s&1] free for sweep s+2
    }

    // Per-thread contraction to two scalars, block-reduce, sliced global adds
    float mp = 0.0f;
#pragma unroll
    for (int k = 0; k < CIN; k++) mp += s1[k] * swsum[k];
    float ep = 0.0f;
#pragma unroll
    for (int k = 0; k < NPAIR; k++) ep += s2[k] * sG2[k];

    smean[tid] = mp;
    sex2[tid] = ep;
    __syncthreads();

    if (tid < PJ) {
        const float m = smean[tid] + smean[tid + 64] + smean[tid + 128] + smean[tid + 192];
        const float e = sex2[tid] + sex2[tid + 64] + sex2[tid + 128] + sex2[tid + 192];
        const int sl = blockIdx.x & (NSLC - 1);
        atomicAdd(&g_pm[sl][tid], m);
        atomicAdd(&g_pe[sl][tid], e);
    }
}

// ---------------------------------------------------------------------------
// Kernel 2: main pass (BN finalize absorbed in prologue; accumulator reset
// absorbed in a ticket-elected epilogue). One warp per TWO consecutive b.
// ---------------------------------------------------------------------------
__global__ __launch_bounds__(256, 3) void k_main(const float* __restrict__ pil,
                                                 const float* __restrict__ W,
                                                 const float* __restrict__ gamma,
                                                 const float* __restrict__ beta,
                                                 float* __restrict__ out) {
    __shared__ ull sW2[(COUT / 2) * 10];        // padded {w_c,w_c+1} rows, 2.5 KB
    __shared__ float sscale[PJ];
    __shared__ float sshift[PJ];
    __shared__ float spill[8][2 * 576];         // 2 rows per warp, 36 KB
    __shared__ int slast;
    const int tid = threadIdx.x;

    // BN finalize from the contracted stats (kernel boundary = full visibility)
    if (tid < PJ) {
        float m = 0.0f, e = 0.0f;
#pragma unroll
        for (int sl = 0; sl < NSLC; sl++) {
            m += __ldcg(&g_pm[sl][tid]);
            e += __ldcg(&g_pe[sl][tid]);
        }
        const float inv = 1.0f / ((float)B_TOT * (float)COUT);
        m *= inv;
        e *= inv;
        const float var = e - m * m;
        const float sc = gamma[tid] * rsqrtf(var + EPSV);
        sscale[tid] = sc;
        sshift[tid] = beta[tid] - m * sc;
    }
    for (int i = tid; i < (COUT / 2) * 10; i += 256) {
        const int cp = i / 10, k = i - cp * 10;
        sW2[i] = (k < CIN) ? pk2(W[(2 * cp) * CIN + k], W[(2 * cp + 1) * CIN + k]) : 0ull;
    }
    __syncthreads();

    const int warp = tid >> 5;
    const int lane = tid & 31;
    const int b0 = (blockIdx.x * 8 + warp) * 2;     // this warp's two b

    // Coalesced stage of two pillar rows (1152 floats = 288 float4).
    {
        const float4* src = (const float4*)(pil + (size_t)b0 * 576);
        float4* dst = (float4*)spill[warp];
#pragma unroll
        for (int r = 0; r < 9; r++) dst[lane + 32 * r] = src[lane + 32 * r];
    }
    __syncwarp();

    // Duplicate-pack each lane's 2x18 floats: {a,a} per channel per n per b.
    const float* vA = spill[warp] + lane * (N_DIM * CIN);
    const float* vB = vA + 576;
    ull pA0[CIN], pA1[CIN], pB0[CIN], pB1[CIN];
#pragma unroll
    for (int k = 0; k < CIN; k++) { float a = vA[k];       pA0[k] = pk2(a, a); }
#pragma unroll
    for (int k = 0; k < CIN; k++) { float a = vA[CIN + k]; pA1[k] = pk2(a, a); }
#pragma unroll
    for (int k = 0; k < CIN; k++) { float a = vB[k];       pB0[k] = pk2(a, a); }
#pragma unroll
    for (int k = 0; k < CIN; k++) { float a = vB[CIN + k]; pB1[k] = pk2(a, a); }

    const float sc0 = sscale[2 * lane], sc1 = sscale[2 * lane + 1];
    const float sh0 = sshift[2 * lane], sh1 = sshift[2 * lane + 1];
    const ull scv0 = pk2(sc0, sc0), shv0 = pk2(sh0, sh0);
    const ull scv1 = pk2(sc1, sc1), shv1 = pk2(sh1, sh1);

    float* obA = out + (size_t)b0 * (COUT * P_DIM) + lane;
    float* obB = obA + COUT * P_DIM;

#pragma unroll 2
    for (int cp = 0; cp < COUT / 2; cp++) {
        const ulonglong2* wr = (const ulonglong2*)(sW2 + cp * 10);
        const ulonglong2 w01 = wr[0], w23 = wr[1], w45 = wr[2], w67 = wr[3];
        const ull w8 = ((const ull*)wr)[8];
        ull wv[CIN] = {w01.x, w01.y, w23.x, w23.y, w45.x, w45.y, w67.x, w67.y, w8};

        ull aA0 = 0ull, aA1 = 0ull, aB0 = 0ull, aB1 = 0ull;
#pragma unroll
        for (int k = 0; k < CIN; k++) {
            asm("fma.rn.f32x2 %0,%1,%2,%0;" : "+l"(aA0) : "l"(pA0[k]), "l"(wv[k]));
            asm("fma.rn.f32x2 %0,%1,%2,%0;" : "+l"(aA1) : "l"(pA1[k]), "l"(wv[k]));
            asm("fma.rn.f32x2 %0,%1,%2,%0;" : "+l"(aB0) : "l"(pB0[k]), "l"(wv[k]));
            asm("fma.rn.f32x2 %0,%1,%2,%0;" : "+l"(aB1) : "l"(pB1[k]), "l"(wv[k]));
        }
        ull yA0, yA1, yB0, yB1;
        asm("fma.rn.f32x2 %0,%1,%2,%3;" : "=l"(yA0) : "l"(aA0), "l"(scv0), "l"(shv0));
        asm("fma.rn.f32x2 %0,%1,%2,%3;" : "=l"(yA1) : "l"(aA1), "l"(scv1), "l"(shv1));
        asm("fma.rn.f32x2 %0,%1,%2,%3;" : "=l"(yB0) : "l"(aB0), "l"(scv0), "l"(shv0));
        asm("fma.rn.f32x2 %0,%1,%2,%3;" : "=l"(yB1) : "l"(aB1), "l"(scv1), "l"(shv1));

        float a0a, a0b, a1a, a1b, b0a, b0b, b1a, b1b;
        upk2(yA0, a0a, a0b);   // channels 2cp, 2cp+1 at n=0 (row A)
        upk2(yA1, a1a, a1b);   // channels 2cp, 2cp+1 at n=1 (row A)
        upk2(yB0, b0a, b0b);
        upk2(yB1, b1a, b1b);
        obA[(2 * cp) * P_DIM]     = fmaxf(fmaxf(a0a, a1a), 0.0f);
        obA[(2 * cp + 1) * P_DIM] = fmaxf(fmaxf(a0b, a1b), 0.0f);
        obB[(2 * cp) * P_DIM]     = fmaxf(fmaxf(b0a, b1a), 0.0f);
        obB[(2 * cp + 1) * P_DIM] = fmaxf(fmaxf(b0b, b1b), 0.0f);
    }

    // Epilogue: last-finishing block zeroes the accumulators for the next
    // call. Safe: ticket == GRIDM-1 implies every block passed its epilogue,
    // hence every prologue read of g_pm/g_pe already happened.
    __syncthreads();
    if (tid == 0) slast = (atomicAdd(&g_t2, 1u) == GRIDM - 1) ? 1 : 0;
    __syncthreads();
    if (slast) {
        if (tid < 256) {
            ((float*)g_pm)[tid] = 0.0f;
            ((float*)g_pm)[tid + 256] = 0.0f;
            ((float*)g_pe)[tid] = 0.0f;
            ((float*)g_pe)[tid + 256] = 0.0f;
        }
        if (tid == 0) g_t2 = 0u;
    }
}

// ---------------------------------------------------------------------------
extern "C" void kernel_launch(void* const* d_in, const int* in_sizes, int n_in,
                              void* d_out, int out_size) {
    const float* pillars = (const float*)d_in[0];
    // d_in[1] = num_points_per_pillar (unused by the reference computation)
    const float* W       = (const float*)d_in[2];
    const float* gamma   = (const float*)d_in[3];
    const float* beta    = (const float*)d_in[4];
    float* out           = (float*)d_out;

    k_stats<<<512, 256>>>(pillars, W);
    k_main<<<GRIDM, 256>>>(pillars, W, gamma, beta, out);
}

// round 11
// speedup vs baseline: 1.0853x; 1.0853x over previous
#include <cuda_runtime.h>

// Problem constants (fixed by reference setup_inputs)
#define B_TOT  16384
#define P_DIM  32
#define N_DIM  2
#define CIN    9
#define COUT   64
#define PJ     64          // P*N = BatchNorm column count
#define NPAIR  45          // upper-tri pairs of 9x9
#define NSLC   8           // global accumulator slices
#define GRIDM  1024        // k_main grid (16 b per block)
#define EPSV   1e-5f

typedef unsigned long long ull;

// Device scratch. Zero at the start of every call (static init on call 1;
// k_main's elected last block re-zeroes before returning).
__device__ float g_pm[NSLC][PJ];     // mean partials (slices)
__device__ float g_pe[NSLC][PJ];     // ex2 partials (slices)
__device__ unsigned g_t2;            // k_main done ticket

// ---------------------------------------------------------------------------
// helpers
// ---------------------------------------------------------------------------
__device__ __forceinline__ ull pk2(float lo, float hi) {
    ull r;
    asm("mov.b64 %0,{%1,%2};" : "=l"(r) : "f"(lo), "f"(hi));
    return r;
}
__device__ __forceinline__ void upk2(ull v, float& lo, float& hi) {
    asm("mov.b64 {%0,%1},%2;" : "=f"(lo), "=f"(hi) : "l"(v));
}
__device__ __forceinline__ void cp16(void* s, const void* g) {
    unsigned sa = (unsigned)__cvta_generic_to_shared(s);
    asm volatile("cp.async.cg.shared.global [%0], [%1], 16;" :: "r"(sa), "l"(g));
}
#define CP_COMMIT() asm volatile("cp.async.commit_group;")
#define CP_WAIT1()  asm volatile("cp.async.wait_group 1;")
#define CP_WAIT0()  asm volatile("cp.async.wait_group 0;")

// ---------------------------------------------------------------------------
// Kernel 1: per-block contracted BN stats (identical to the passing body).
// 512 blocks x 256 threads, 4 sweeps of 8 rows, cp.async double-buffered.
// ---------------------------------------------------------------------------
__global__ __launch_bounds__(256) void k_stats(const float* __restrict__ pil,
                                               const float* __restrict__ W) {
    __shared__ float4 buf[2][1152];          // 2 x 8 rows x 576 floats = 36.9 KB
    __shared__ float sG2[NPAIR];
    __shared__ float swsum[CIN];
    __shared__ float smean[256];
    __shared__ float sex2[256];
    const int tid = threadIdx.x;
    const int j = tid & 63;
    const int g = tid >> 6;                  // 0..3

    // Stage sweep 0 asynchronously
    {
        const float4* src = (const float4*)(pil + (size_t)(blockIdx.x * 8) * 576);
        for (int i = tid; i < 1152; i += 256) cp16(&buf[0][i], &src[i]);
        CP_COMMIT();
    }

    // Gram (doubled off-diagonals) + column sums of W — overlaps the cp.async
    if (tid < NPAIR) {
        int c1 = 0, c2 = 0, idx = 0;
#pragma unroll
        for (int a = 0; a < CIN; a++)
#pragma unroll
            for (int b2 = a; b2 < CIN; b2++) {
                if (idx == tid) { c1 = a; c2 = b2; }
                idx++;
            }
        float s = 0.0f;
        for (int o = 0; o < COUT; o++) s += W[o * CIN + c1] * W[o * CIN + c2];
        sG2[tid] = (c1 == c2 ? 1.0f : 2.0f) * s;
    } else if (tid < NPAIR + CIN) {
        const int c = tid - NPAIR;
        float s = 0.0f;
        for (int o = 0; o < COUT; o++) s += W[o * CIN + c];
        swsum[c] = s;
    }

    float s1[CIN];
    float s2[NPAIR];
#pragma unroll
    for (int k = 0; k < CIN; k++) s1[k] = 0.0f;
#pragma unroll
    for (int k = 0; k < NPAIR; k++) s2[k] = 0.0f;

    for (int s = 0; s < 4; s++) {
        if (s < 3) {
            const float4* src =
                (const float4*)(pil + (size_t)((s + 1) * 4096 + blockIdx.x * 8) * 576);
            for (int i = tid; i < 1152; i += 256) cp16(&buf[(s + 1) & 1][i], &src[i]);
            CP_COMMIT();
            CP_WAIT1();                      // sweep s complete, s+1 may be in flight
        } else {
            CP_WAIT0();
        }
        __syncthreads();

        const float* base = (const float*)buf[s & 1];
#pragma unroll
        for (int half = 0; half < 2; half++) {
            const float* v = base + (g + 4 * half) * 576 + j * CIN;
            float vv[CIN];
#pragma unroll
            for (int k = 0; k < CIN; k++) vv[k] = v[k];
            int idx = 0;
#pragma unroll
            for (int c1 = 0; c1 < CIN; c1++) {
                s1[c1] += vv[c1];
#pragma unroll
                for (int c2 = c1; c2 < CIN; c2++) { s2[idx] += vv[c1] * vv[c2]; idx++; }
            }
        }
        __syncthreads();                     // buf[s&1] free for sweep s+2
    }

    // Per-thread contraction to two scalars, block-reduce, sliced global adds
    float mp = 0.0f;
#pragma unroll
    for (int k = 0; k < CIN; k++) mp += s1[k] * swsum[k];
    float ep = 0.0f;
#pragma unroll
    for (int k = 0; k < NPAIR; k++) ep += s2[k] * sG2[k];

    smean[tid] = mp;
    sex2[tid] = ep;
    __syncthreads();

    if (tid < PJ) {
        const float m = smean[tid] + smean[tid + 64] + smean[tid + 128] + smean[tid + 192];
        const float e = sex2[tid] + sex2[tid + 64] + sex2[tid + 128] + sex2[tid + 192];
        const int sl = blockIdx.x & (NSLC - 1);
        atomicAdd(&g_pm[sl][tid], m);
        atomicAdd(&g_pe[sl][tid], e);
    }
}

// ---------------------------------------------------------------------------
// Kernel 2: main pass.
//   Preamble (overlaps k_stats tail via PDL): cp.async stage of this block's
//   16 pillar rows + sW2 fill. Then griddepcontrol.wait -> BN finalize ->
//   barrier -> per-warp packed-f32x2 compute -> ticket-elected reset.
// ---------------------------------------------------------------------------
__global__ __launch_bounds__(256, 3) void k_main(const float* __restrict__ pil,
                                                 const float* __restrict__ W,
                                                 const float* __restrict__ gamma,
                                                 const float* __restrict__ beta,
                                                 float* __restrict__ out) {
    __shared__ ull sW2[(COUT / 2) * 10];        // padded {w_c,w_c+1} rows, 2.5 KB
    __shared__ float sscale[PJ];
    __shared__ float sshift[PJ];
    __shared__ float spill[8][2 * 576];         // 16 pillar rows, 36.9 KB
    __shared__ int slast;
    const int tid = threadIdx.x;

    // ---- preamble (independent of k_stats results) ----
    {
        const float4* src = (const float4*)(pil + (size_t)blockIdx.x * 16 * 576);
        float4* dst = (float4*)&spill[0][0];
#pragma unroll
        for (int r = 0; r < 9; r++) cp16(&dst[tid + 256 * r], &src[tid + 256 * r]);
        CP_COMMIT();
    }
    for (int i = tid; i < (COUT / 2) * 10; i += 256) {
        const int cp = i / 10, k = i - cp * 10;
        sW2[i] = (k < CIN) ? pk2(W[(2 * cp) * CIN + k], W[(2 * cp + 1) * CIN + k]) : 0ull;
    }

    // ---- wait for k_stats grid (PDL) then finalize BN ----
    asm volatile("griddepcontrol.wait;" ::: "memory");
    if (tid < PJ) {
        float m = 0.0f, e = 0.0f;
#pragma unroll
        for (int sl = 0; sl < NSLC; sl++) {
            m += __ldcg(&g_pm[sl][tid]);
            e += __ldcg(&g_pe[sl][tid]);
        }
        const float inv = 1.0f / ((float)B_TOT * (float)COUT);
        m *= inv;
        e *= inv;
        const float var = e - m * m;
        const float sc = gamma[tid] * rsqrtf(var + EPSV);
        sscale[tid] = sc;
        sshift[tid] = beta[tid] - m * sc;
    }
    CP_WAIT0();
    __syncthreads();

    const int warp = tid >> 5;
    const int lane = tid & 31;
    const int b0 = (blockIdx.x * 8 + warp) * 2;     // this warp's two b

    // Duplicate-pack each lane's 2x18 floats: {a,a} per channel per n per b.
    const float* vA = spill[warp] + lane * (N_DIM * CIN);
    const float* vB = vA + 576;
    ull pA0[CIN], pA1[CIN], pB0[CIN], pB1[CIN];
#pragma unroll
    for (int k = 0; k < CIN; k++) { float a = vA[k];       pA0[k] = pk2(a, a); }
#pragma unroll
    for (int k = 0; k < CIN; k++) { float a = vA[CIN + k]; pA1[k] = pk2(a, a); }
#pragma unroll
    for (int k = 0; k < CIN; k++) { float a = vB[k];       pB0[k] = pk2(a, a); }
#pragma unroll
    for (int k = 0; k < CIN; k++) { float a = vB[CIN + k]; pB1[k] = pk2(a, a); }

    const float sc0 = sscale[2 * lane], sc1 = sscale[2 * lane + 1];
    const float sh0 = sshift[2 * lane], sh1 = sshift[2 * lane + 1];
    const ull scv0 = pk2(sc0, sc0), shv0 = pk2(sh0, sh0);
    const ull scv1 = pk2(sc1, sc1), shv1 = pk2(sh1, sh1);

    float* obA = out + (size_t)b0 * (COUT * P_DIM) + lane;
    float* obB = obA + COUT * P_DIM;

#pragma unroll 2
    for (int cp = 0; cp < COUT / 2; cp++) {
        const ulonglong2* wr = (const ulonglong2*)(sW2 + cp * 10);
        const ulonglong2 w01 = wr[0], w23 = wr[1], w45 = wr[2], w67 = wr[3];
        const ull w8 = ((const ull*)wr)[8];
        ull wv[CIN] = {w01.x, w01.y, w23.x, w23.y, w45.x, w45.y, w67.x, w67.y, w8};

        ull aA0 = 0ull, aA1 = 0ull, aB0 = 0ull, aB1 = 0ull;
#pragma unroll
        for (int k = 0; k < CIN; k++) {
            asm("fma.rn.f32x2 %0,%1,%2,%0;" : "+l"(aA0) : "l"(pA0[k]), "l"(wv[k]));
            asm("fma.rn.f32x2 %0,%1,%2,%0;" : "+l"(aA1) : "l"(pA1[k]), "l"(wv[k]));
            asm("fma.rn.f32x2 %0,%1,%2,%0;" : "+l"(aB0) : "l"(pB0[k]), "l"(wv[k]));
            asm("fma.rn.f32x2 %0,%1,%2,%0;" : "+l"(aB1) : "l"(pB1[k]), "l"(wv[k]));
        }
        ull yA0, yA1, yB0, yB1;
        asm("fma.rn.f32x2 %0,%1,%2,%3;" : "=l"(yA0) : "l"(aA0), "l"(scv0), "l"(shv0));
        asm("fma.rn.f32x2 %0,%1,%2,%3;" : "=l"(yA1) : "l"(aA1), "l"(scv1), "l"(shv1));
        asm("fma.rn.f32x2 %0,%1,%2,%3;" : "=l"(yB0) : "l"(aB0), "l"(scv0), "l"(shv0));
        asm("fma.rn.f32x2 %0,%1,%2,%3;" : "=l"(yB1) : "l"(aB1), "l"(scv1), "l"(shv1));

        float a0a, a0b, a1a, a1b, b0a, b0b, b1a, b1b;
        upk2(yA0, a0a, a0b);   // channels 2cp, 2cp+1 at n=0 (row A)
        upk2(yA1, a1a, a1b);   // channels 2cp, 2cp+1 at n=1 (row A)
        upk2(yB0, b0a, b0b);
        upk2(yB1, b1a, b1b);
        obA[(2 * cp) * P_DIM]     = fmaxf(fmaxf(a0a, a1a), 0.0f);
        obA[(2 * cp + 1) * P_DIM] = fmaxf(fmaxf(a0b, a1b), 0.0f);
        obB[(2 * cp) * P_DIM]     = fmaxf(fmaxf(b0a, b1a), 0.0f);
        obB[(2 * cp + 1) * P_DIM] = fmaxf(fmaxf(b0b, b1b), 0.0f);
    }

    // Epilogue: last-finishing block zeroes the accumulators for the next
    // call. Safe: ticket == GRIDM-1 implies every block passed its epilogue,
    // hence every prologue read of g_pm/g_pe already happened.
    __syncthreads();
    if (tid == 0) slast = (atomicAdd(&g_t2, 1u) == GRIDM - 1) ? 1 : 0;
    __syncthreads();
    if (slast) {
        if (tid < 256) {
            ((float*)g_pm)[tid] = 0.0f;
            ((float*)g_pm)[tid + 256] = 0.0f;
            ((float*)g_pe)[tid] = 0.0f;
            ((float*)g_pe)[tid + 256] = 0.0f;
        }
        if (tid == 0) g_t2 = 0u;
    }
}

// ---------------------------------------------------------------------------
extern "C" void kernel_launch(void* const* d_in, const int* in_sizes, int n_in,
                              void* d_out, int out_size) {
    const float* pillars = (const float*)d_in[0];
    // d_in[1] = num_points_per_pillar (unused by the reference computation)
    const float* W       = (const float*)d_in[2];
    const float* gamma   = (const float*)d_in[3];
    const float* beta    = (const float*)d_in[4];
    float* out           = (float*)d_out;

    k_stats<<<512, 256>>>(pillars, W);

    // k_main with programmatic dependent launch: its preamble (pillar staging
    // + weight packing) overlaps k_stats' tail; griddepcontrol.wait orders the
    // g_pm/g_pe reads after k_stats completion.
    cudaLaunchConfig_t cfg = {};
    cfg.gridDim = dim3(GRIDM, 1, 1);
    cfg.blockDim = dim3(256, 1, 1);
    cfg.dynamicSmemBytes = 0;
    cfg.stream = 0;
    cudaLaunchAttribute attrs[1];
    attrs[0].id = cudaLaunchAttributeProgrammaticStreamSerialization;
    attrs[0].val.programmaticStreamSerializationAllowed = 1;
    cfg.attrs = attrs;
    cfg.numAttrs = 1;
    cudaLaunchKernelEx(&cfg, k_main, pillars, W, gamma, beta, out);
}